// round 2
// baseline (speedup 1.0000x reference)
#include <cuda_runtime.h>
#include <math.h>

#define NNODE 856
#define NEDGE 2896
#define NSEQ  1696
#define NHF   128
#define NNF_  17
#define DM    160
#define SEQL  107
#define NLAY  10
#define WCN   1408
#define EPSF  1e-5f

// ---------------- device scratch (no allocations allowed) ----------------
__device__ float g_dinv[NNODE];
__device__ float g_tx1[NNODE * NNF_];
__device__ float g_tx2[NNODE * NNF_];
__device__ float g_h[NNODE * NHF];
__device__ float g_hin[NNODE * NHF];
__device__ float g_B[NLAY * 10 * 32];
__device__ float g_Wc[NLAY * NHF * WCN];     // [l][i][j*128+o]; j<10: zs weights, j=10: root_w
__device__ float g_P[NNODE * WCN];
__device__ int   g_cnt[NNODE];
__device__ int   g_rp[NNODE + 1];
__device__ int   g_eid[NEDGE];
__device__ float g_t[NNODE * DM];
__device__ float g_qkv[NNODE * 480];
__device__ float g_att[NNODE * DM];
__device__ float g_obuf[NNODE * DM];
__device__ float g_f1[NNODE * 256];

// ---------------- Cheb prep ----------------
__global__ void k_dinv(const int* __restrict__ ss) {
    int n = blockIdx.x * blockDim.x + threadIdx.x;
    if (n >= NNODE) return;
    int c = 0;
    for (int e = 0; e < NSEQ; e++) c += (ss[e] == n);
    g_dinv[n] = (c > 0) ? rsqrtf((float)c) : 0.f;
}

// mode 0: g_tx1 = lap(x);  mode 1: g_tx2 = 2*lap(g_tx1) - x
__global__ void k_lap(const int* __restrict__ ss, const int* __restrict__ sd,
                      const float* __restrict__ x, int mode) {
    int n = blockIdx.x;
    int f = threadIdx.x;
    if (f >= NNF_) return;
    const float* in = (mode == 0) ? x : g_tx1;
    float dn = g_dinv[n];
    float acc = 0.f;
    for (int e = 0; e < NSEQ; e++) {
        if (sd[e] == n) {
            int s = ss[e];
            acc += -(g_dinv[s] * dn) * in[s * NNF_ + f];
        }
    }
    if (mode == 0) g_tx1[n * NNF_ + f] = acc;
    else           g_tx2[n * NNF_ + f] = 2.f * acc - x[n * NNF_ + f];
}

__global__ void k_chebout(const float* __restrict__ x, const float* __restrict__ cw,
                          const float* __restrict__ cb) {
    int n = blockIdx.x, o = threadIdx.x;
    const float* xr = x + n * NNF_;
    const float* t1 = g_tx1 + n * NNF_;
    const float* t2 = g_tx2 + n * NNF_;
    float acc = cb[o];
#pragma unroll
    for (int f = 0; f < NNF_; f++) {
        acc += xr[f] * cw[f * NHF + o];
        acc += t1[f] * cw[2176 + f * NHF + o];
        acc += t2[f] * cw[4352 + f * NHF + o];
    }
    g_hin[n * NHF + o] = acc;   // input to NNConv layer 0
}

// ---------------- CSR build (deterministic, no atomics) ----------------
__global__ void k_ecount(const int* __restrict__ ed) {
    int n = blockIdx.x * blockDim.x + threadIdx.x;
    if (n >= NNODE) return;
    int c = 0;
    for (int e = 0; e < NEDGE; e++) c += (ed[e] == n);
    g_cnt[n] = c;
}

__global__ void k_escan() {
    __shared__ int s[1024];
    int t = threadIdx.x;
    s[t] = (t < NNODE) ? g_cnt[t] : 0;
    __syncthreads();
    for (int off = 1; off < 1024; off <<= 1) {
        int v = (t >= off) ? s[t - off] : 0;
        __syncthreads();
        s[t] += v;
        __syncthreads();
    }
    if (t == 0) g_rp[0] = 0;
    if (t < NNODE) g_rp[t + 1] = s[t];
}

__global__ void k_efill(const int* __restrict__ ed) {
    int n = blockIdx.x * blockDim.x + threadIdx.x;
    if (n >= NNODE) return;
    int p = g_rp[n];
    for (int e = 0; e < NEDGE; e++)
        if (ed[e] == n) g_eid[p++] = e;
}

// ---------------- affine edge-MLP collapse ----------------
// B[l][j][t] = sum_u A[j][u]*w1[l][u][t] + (j==9)*b1[l][t];  A[j<9]=ee_w row, A[9]=ee_b
__global__ void k_B(const float* __restrict__ eew, const float* __restrict__ eeb,
                    const float* __restrict__ w1, const float* __restrict__ b1) {
    int t = threadIdx.x;           // 320 threads
    int j = t >> 5, tc = t & 31;
    for (int l = 0; l < NLAY; l++) {
        float acc = (j == 9) ? b1[l * 32 + tc] : 0.f;
        for (int u = 0; u < 32; u++) {
            float a = (j < 9) ? eew[j * 32 + u] : eeb[u];
            acc += a * w1[(l * 32 + u) * 32 + tc];
        }
        g_B[l * 320 + j * 32 + tc] = acc;
    }
}

// Wc[l][i][j*128+o] = sum_t B[l][j][t]*w2[l][t][i*128+o]  (+b2 at j==9)
__global__ void k_Wc(const float* __restrict__ w2, const float* __restrict__ b2) {
    __shared__ float Bs[320];
    int l = blockIdx.y;
    int io = blockIdx.x * blockDim.x + threadIdx.x;   // 0..16383
    for (int i = threadIdx.x; i < 320; i += blockDim.x) Bs[i] = g_B[l * 320 + i];
    __syncthreads();
    float acc[10];
#pragma unroll
    for (int j = 0; j < 10; j++) acc[j] = 0.f;
    const float* wp = w2 + (size_t)l * 32 * 16384 + io;
    for (int tc = 0; tc < 32; tc++) {
        float v = wp[(size_t)tc * 16384];
#pragma unroll
        for (int j = 0; j < 10; j++) acc[j] += Bs[j * 32 + tc] * v;
    }
    acc[9] += b2[(size_t)l * 16384 + io];
    int i = io >> 7, o = io & 127;
    float* dst = g_Wc + (size_t)l * NHF * WCN + i * WCN + o;
#pragma unroll
    for (int j = 0; j < 10; j++) dst[j * 128] = acc[j];
}

__global__ void k_root(const float* __restrict__ rw) {
    int idx = blockIdx.x * blockDim.x + threadIdx.x;
    if (idx >= NLAY * 16384) return;
    int l = idx >> 14, io = idx & 16383;
    int i = io >> 7, o = io & 127;
    g_Wc[(size_t)l * NHF * WCN + i * WCN + 1280 + o] = rw[idx];
}

// ---------------- generic fp32 tiled GEMM: C = act(A@B + bias) ----------------
// K must be a multiple of 16 (true for 128/160/256 here)
__global__ void sgemm(const float* __restrict__ A, const float* __restrict__ B,
                      const float* __restrict__ bias, float* __restrict__ C,
                      int M, int N, int K, int act) {
    __shared__ float As[16][64];
    __shared__ float Bs[16][64];
    int tid = threadIdx.x;
    int tx = tid & 15, ty = tid >> 4;
    int rb = blockIdx.y * 64, cb = blockIdx.x * 64;
    float acc[4][4];
#pragma unroll
    for (int i = 0; i < 4; i++)
#pragma unroll
        for (int j = 0; j < 4; j++) acc[i][j] = 0.f;

    for (int k0 = 0; k0 < K; k0 += 16) {
#pragma unroll 4
        for (int i = tid; i < 1024; i += 256) {
            int m = i >> 4, k = i & 15;
            int gr = rb + m;
            As[k][m] = (gr < M) ? A[gr * K + k0 + k] : 0.f;
        }
#pragma unroll 4
        for (int i = tid; i < 1024; i += 256) {
            int k = i >> 6, c = i & 63;
            int gc = cb + c;
            Bs[k][c] = (gc < N) ? B[(k0 + k) * N + gc] : 0.f;
        }
        __syncthreads();
#pragma unroll
        for (int k = 0; k < 16; k++) {
            float av[4], bv[4];
#pragma unroll
            for (int i = 0; i < 4; i++) av[i] = As[k][ty * 4 + i];
#pragma unroll
            for (int j = 0; j < 4; j++) bv[j] = Bs[k][tx * 4 + j];
#pragma unroll
            for (int i = 0; i < 4; i++)
#pragma unroll
                for (int j = 0; j < 4; j++) acc[i][j] += av[i] * bv[j];
        }
        __syncthreads();
    }
#pragma unroll
    for (int i = 0; i < 4; i++) {
        int r = rb + ty * 4 + i;
        if (r >= M) continue;
#pragma unroll
        for (int j = 0; j < 4; j++) {
            int c = cb + tx * 4 + j;
            if (c >= N) continue;
            float v = acc[i][j];
            if (bias) v += bias[c];
            if (act) v = fmaxf(v, 0.f);
            C[r * N + c] = v;
        }
    }
}

// ---------------- NNConv gather + residual + LN + GELU ----------------
__global__ void k_conv_node(int l, const int* __restrict__ esrc,
                            const float* __restrict__ eattr,
                            const float* __restrict__ conv_b,
                            const float* __restrict__ lng,
                            const float* __restrict__ lnb) {
    int n = blockIdx.x, o = threadIdx.x;   // 128 threads
    float acc = g_P[n * WCN + 1280 + o] + conv_b[l * 128 + o];
    int e0 = g_rp[n], e1 = g_rp[n + 1];
    for (int idx = e0; idx < e1; idx++) {
        int e = g_eid[idx];
        int s = esrc[e];
        const float* zp = eattr + e * 9;
        const float* Ps = g_P + s * WCN + o;
        float m = Ps[1152];                   // zs[9] = 1 term
#pragma unroll
        for (int j = 0; j < 9; j++) m += zp[j] * Ps[j * 128];
        acc += m;
    }
    float nh = acc + ((l > 0) ? g_h[n * 128 + o] : 0.f);
    g_h[n * 128 + o] = nh;

    // LayerNorm over 128 + GELU, write next layer's GEMM input
    float a = nh, b = nh * nh;
#pragma unroll
    for (int off = 16; off; off >>= 1) {
        a += __shfl_down_sync(0xffffffffu, a, off);
        b += __shfl_down_sync(0xffffffffu, b, off);
    }
    __shared__ float sa[4], sb[4];
    int w = o >> 5, lane = o & 31;
    if (lane == 0) { sa[w] = a; sb[w] = b; }
    __syncthreads();
    if (o == 0) {
        float ta = sa[0] + sa[1] + sa[2] + sa[3];
        float tb = sb[0] + sb[1] + sb[2] + sb[3];
        sa[0] = ta * (1.f / 128.f);
        sb[0] = tb * (1.f / 128.f);
    }
    __syncthreads();
    float mean = sa[0];
    float var = sb[0] - mean * mean;
    int ni = (l + 1) % NLAY;
    float z = (nh - mean) * rsqrtf(var + EPSF) * lng[ni * 128 + o] + lnb[ni * 128 + o];
    g_hin[n * 128 + o] = 0.5f * z * (1.f + erff(z * 0.70710678118654752f));
}

// ---------------- concat with sinusoidal positions ----------------
__global__ void k_concat() {
    int n = blockIdx.x, c = threadIdx.x;   // 160 threads
    float v;
    if (c < 128) {
        v = g_hin[n * 128 + c];
    } else {
        int p = n % SEQL;
        int cc = c - 128;
        int i = cc >> 1;
        float div = expf((float)(2 * i) * (-0.28782313662425576f));  // -ln(1e4)/32
        float ang = (float)p * div;
        v = (cc & 1) ? cosf(ang) : sinf(ang);
    }
    g_t[n * DM + c] = v;
}

// ---------------- attention: one block per (batch, head) ----------------
__global__ void k_attn() {
    int bh = blockIdx.x;
    int b = bh >> 3, h = bh & 7;
    __shared__ float Ks[SEQL * 20];
    __shared__ float Vs[SEQL * 20];
    int tid = threadIdx.x;   // 128
    for (int i = tid; i < SEQL * 20; i += 128) {
        int r = i / 20, d = i % 20;
        int n = b * SEQL + r;
        Ks[i] = g_qkv[n * 480 + 160 + h * 20 + d];
        Vs[i] = g_qkv[n * 480 + 320 + h * 20 + d];
    }
    __syncthreads();
    if (tid >= SEQL) return;
    int n = b * SEQL + tid;
    float q[20];
#pragma unroll
    for (int d = 0; d < 20; d++)
        q[d] = g_qkv[n * 480 + h * 20 + d] * 0.22360679774997896f;  // 1/sqrt(20)
    float m = -1e30f;
    for (int k = 0; k < SEQL; k++) {
        float s = 0.f;
#pragma unroll
        for (int d = 0; d < 20; d++) s += q[d] * Ks[k * 20 + d];
        m = fmaxf(m, s);
    }
    float lsum = 0.f, acc[20];
#pragma unroll
    for (int d = 0; d < 20; d++) acc[d] = 0.f;
    for (int k = 0; k < SEQL; k++) {
        float s = 0.f;
#pragma unroll
        for (int d = 0; d < 20; d++) s += q[d] * Ks[k * 20 + d];
        float p = expf(s - m);
        lsum += p;
#pragma unroll
        for (int d = 0; d < 20; d++) acc[d] += p * Vs[k * 20 + d];
    }
    float inv = 1.f / lsum;
#pragma unroll
    for (int d = 0; d < 20; d++) g_att[n * DM + h * 20 + d] = acc[d] * inv;
}

// ---------------- residual + LayerNorm over 160 (t += g_obuf; t = ln(t)) -------
__global__ void k_lnres(const float* __restrict__ g, const float* __restrict__ bb) {
    int n = blockIdx.x, c = threadIdx.x;  // 160 threads (5 warps)
    float v = g_t[n * DM + c] + g_obuf[n * DM + c];
    float a = v, sq = v * v;
#pragma unroll
    for (int off = 16; off; off >>= 1) {
        a  += __shfl_down_sync(0xffffffffu, a,  off);
        sq += __shfl_down_sync(0xffffffffu, sq, off);
    }
    __shared__ float sa[5], sb[5];
    int w = c >> 5, lane = c & 31;
    if (lane == 0) { sa[w] = a; sb[w] = sq; }
    __syncthreads();
    if (c == 0) {
        float ta = 0.f, tb = 0.f;
        for (int i = 0; i < 5; i++) { ta += sa[i]; tb += sb[i]; }
        sa[0] = ta * (1.f / 160.f);
        sb[0] = tb * (1.f / 160.f);
    }
    __syncthreads();
    float mean = sa[0];
    float var = sb[0] - mean * mean;
    g_t[n * DM + c] = (v - mean) * rsqrtf(var + EPSF) * g[c] + bb[c];
}

// ---------------- final linear head (N=3) ----------------
__global__ void k_final(const float* __restrict__ lw, const float* __restrict__ lb,
                        float* __restrict__ out) {
    int n = blockIdx.x * blockDim.x + threadIdx.x;
    if (n >= NNODE) return;
    float a0 = lb[0], a1 = lb[1], a2 = lb[2];
    const float* tr = g_t + n * DM;
#pragma unroll 4
    for (int k = 0; k < DM; k++) {
        float v = tr[k];
        a0 += v * lw[k * 3 + 0];
        a1 += v * lw[k * 3 + 1];
        a2 += v * lw[k * 3 + 2];
    }
    out[n * 3 + 0] = a0;
    out[n * 3 + 1] = a1;
    out[n * 3 + 2] = a2;
}

// ---------------- host ----------------
extern "C" void kernel_launch(void* const* d_in, const int* in_sizes, int n_in,
                              void* d_out, int out_size) {
    const float* x      = (const float*)d_in[0];
    const float* eattr  = (const float*)d_in[1];
    const float* cheb_w = (const float*)d_in[2];
    const float* cheb_b = (const float*)d_in[3];
    const float* ee_w   = (const float*)d_in[4];
    const float* ee_b   = (const float*)d_in[5];
    const float* w1     = (const float*)d_in[6];
    const float* b1     = (const float*)d_in[7];
    const float* w2     = (const float*)d_in[8];
    const float* b2     = (const float*)d_in[9];
    const float* root_w = (const float*)d_in[10];
    const float* conv_b = (const float*)d_in[11];
    const float* ln_g   = (const float*)d_in[12];
    const float* ln_b   = (const float*)d_in[13];
    const float* aiw    = (const float*)d_in[14];
    const float* aib    = (const float*)d_in[15];
    const float* aow    = (const float*)d_in[16];
    const float* aob    = (const float*)d_in[17];
    const float* fw1    = (const float*)d_in[18];
    const float* fb1    = (const float*)d_in[19];
    const float* fw2    = (const float*)d_in[20];
    const float* fb2    = (const float*)d_in[21];
    const float* l1g    = (const float*)d_in[22];
    const float* l1b    = (const float*)d_in[23];
    const float* l2g    = (const float*)d_in[24];
    const float* l2b    = (const float*)d_in[25];
    const float* lw     = (const float*)d_in[26];
    const float* lb     = (const float*)d_in[27];
    const int*   seq    = (const int*)d_in[28];
    const int*   ei     = (const int*)d_in[29];
    const int *ss = seq, *sd = seq + NSEQ;
    const int *esrc = ei, *edst = ei + NEDGE;
    float* out = (float*)d_out;

    float *p_hin, *p_Wc, *p_P, *p_t, *p_qkv, *p_att, *p_obuf, *p_f1;
    cudaGetSymbolAddress((void**)&p_hin,  g_hin);
    cudaGetSymbolAddress((void**)&p_Wc,   g_Wc);
    cudaGetSymbolAddress((void**)&p_P,    g_P);
    cudaGetSymbolAddress((void**)&p_t,    g_t);
    cudaGetSymbolAddress((void**)&p_qkv,  g_qkv);
    cudaGetSymbolAddress((void**)&p_att,  g_att);
    cudaGetSymbolAddress((void**)&p_obuf, g_obuf);
    cudaGetSymbolAddress((void**)&p_f1,   g_f1);

    // Cheb + CSR + edge-MLP collapse
    k_dinv<<<4, 256>>>(ss);
    k_lap<<<NNODE, 32>>>(ss, sd, x, 0);
    k_lap<<<NNODE, 32>>>(ss, sd, x, 1);
    k_chebout<<<NNODE, 128>>>(x, cheb_w, cheb_b);
    k_ecount<<<4, 256>>>(edst);
    k_escan<<<1, 1024>>>();
    k_efill<<<4, 256>>>(edst);
    k_B<<<1, 320>>>(ee_w, ee_b, w1, b1);
    k_Wc<<<dim3(64, 10), 256>>>(w2, b2);
    k_root<<<640, 256>>>(root_w);

    // 10 NNConv layers
    for (int l = 0; l < NLAY; l++) {
        sgemm<<<dim3(22, 14), 256>>>(p_hin, p_Wc + (size_t)l * NHF * WCN, nullptr,
                                     p_P, NNODE, WCN, NHF, 0);
        k_conv_node<<<NNODE, 128>>>(l, esrc, eattr, conv_b, ln_g, ln_b);
    }

    k_concat<<<NNODE, 160>>>();

    // 3 transformer layers
    for (int tl = 0; tl < 3; tl++) {
        sgemm<<<dim3(8, 14), 256>>>(p_t, aiw + (size_t)tl * 160 * 480,
                                    aib + tl * 480, p_qkv, NNODE, 480, 160, 0);
        k_attn<<<64, 128>>>();
        sgemm<<<dim3(3, 14), 256>>>(p_att, aow + (size_t)tl * 160 * 160,
                                    aob + tl * 160, p_obuf, NNODE, 160, 160, 0);
        k_lnres<<<NNODE, 160>>>(l1g + tl * 160, l1b + tl * 160);
        sgemm<<<dim3(4, 14), 256>>>(p_t, fw1 + (size_t)tl * 160 * 256,
                                    fb1 + tl * 256, p_f1, NNODE, 256, 160, 1);
        sgemm<<<dim3(3, 14), 256>>>(p_f1, fw2 + (size_t)tl * 256 * 160,
                                    fb2 + tl * 160, p_obuf, NNODE, 160, 256, 0);
        k_lnres<<<NNODE, 160>>>(l2g + tl * 160, l2b + tl * 160);
    }

    k_final<<<4, 256>>>(lw, lb, out);
}

// round 3
// speedup vs baseline: 1.1500x; 1.1500x over previous
#include <cuda_runtime.h>
#include <math.h>

#define NNODE 856
#define NEDGE 2896
#define NSEQ  1696
#define NHF   128
#define NNF_  17
#define DM    160
#define SEQL  107
#define NLAY  10
#define WCN   1408
#define EPSF  1e-5f
#define NB    296
#define NT    256
#define NTH   (NB*NT)

// ---------------- device scratch ----------------
__device__ float g_dinv[NNODE];
__device__ int   g_degi[NNODE];
__device__ float g_tx1[NNODE * NNF_];
__device__ float g_tx2[NNODE * NNF_];
__device__ float g_h[NNODE * NHF];
__device__ float g_hin[NNODE * NHF];
__device__ float g_Bm[NLAY * 320];
__device__ float g_Wc[NLAY * NHF * WCN];
__device__ float g_P[NNODE * WCN];
__device__ int   g_cnti[NNODE];
__device__ int   g_rp[NNODE + 1];
__device__ int   g_eid[NEDGE];
__device__ float g_t[NNODE * DM];
__device__ float g_qkv[NNODE * 480];
__device__ float g_att[NNODE * DM];
__device__ unsigned g_barcnt;
__device__ volatile unsigned g_bargen;

// ---------------- grid barrier (co-resident persistent grid) ----------------
__device__ __forceinline__ void gbar() {
    __syncthreads();
    __threadfence();                       // publish my writes to L2
    if (threadIdx.x == 0) {
        unsigned gen = g_bargen;
        if (atomicAdd(&g_barcnt, 1u) == NB - 1u) {
            g_barcnt = 0u;
            __threadfence();
            g_bargen = gen + 1u;
        } else {
            while (g_bargen == gen) __nanosleep(32);
        }
    }
    __syncthreads();
    __threadfence();                       // gpu-scope fence -> CCTL.IVALL: invalidate stale L1
}

__device__ __forceinline__ float geluf(float x) {
    return 0.5f * x * (1.0f + erff(x * 0.70710678118654752f));
}

// ---------------- tiled GEMM phase: C = act(A@B + bias), tiles over blocks ---
__device__ void gemm_tiles(const float* __restrict__ A, const float* __restrict__ B,
                           const float* __restrict__ bias, float* __restrict__ C,
                           int M, int N, int K, int act, float* SB) {
    float* As = SB;            // [16][64]
    float* Bs = SB + 1024;     // [16][64]
    int ntc = (N + 63) >> 6;
    int ntiles = ((M + 63) >> 6) * ntc;
    int tid = threadIdx.x;
    int tx = tid & 15, ty = tid >> 4;
    for (int t = blockIdx.x; t < ntiles; t += NB) {
        int tr = t / ntc;
        int rb = tr * 64, cb = (t - tr * ntc) * 64;
        float acc[4][4];
#pragma unroll
        for (int i = 0; i < 4; i++)
#pragma unroll
            for (int j = 0; j < 4; j++) acc[i][j] = 0.f;
        for (int k0 = 0; k0 < K; k0 += 16) {
#pragma unroll 4
            for (int i = tid; i < 1024; i += NT) {
                int m = i >> 4, k = i & 15;
                int gr = rb + m;
                As[k * 64 + m] = (gr < M) ? A[gr * K + k0 + k] : 0.f;
            }
#pragma unroll 4
            for (int i = tid; i < 1024; i += NT) {
                int k = i >> 6, c = i & 63;
                int gc = cb + c;
                Bs[k * 64 + c] = (gc < N) ? B[(k0 + k) * N + gc] : 0.f;
            }
            __syncthreads();
#pragma unroll
            for (int k = 0; k < 16; k++) {
                float4 a4 = *(const float4*)&As[k * 64 + ty * 4];
                float4 b4 = *(const float4*)&Bs[k * 64 + tx * 4];
                float av[4] = {a4.x, a4.y, a4.z, a4.w};
                float bv[4] = {b4.x, b4.y, b4.z, b4.w};
#pragma unroll
                for (int i = 0; i < 4; i++)
#pragma unroll
                    for (int j = 0; j < 4; j++) acc[i][j] += av[i] * bv[j];
            }
            __syncthreads();
        }
#pragma unroll
        for (int i = 0; i < 4; i++) {
            int r = rb + ty * 4 + i;
            if (r >= M) continue;
#pragma unroll
            for (int j = 0; j < 4; j++) {
                int c = cb + tx * 4 + j;
                if (c >= N) continue;
                float v = acc[i][j];
                if (bias) v += bias[c];
                if (act) v = fmaxf(v, 0.f);
                C[r * N + c] = v;
            }
        }
    }
}

// ---------------- the one kernel ----------------
__global__ void __launch_bounds__(NT, 2)
mega(const float* __restrict__ x, const float* __restrict__ eattr,
     const float* __restrict__ cheb_w, const float* __restrict__ cheb_b,
     const float* __restrict__ eew, const float* __restrict__ eeb,
     const float* __restrict__ w1, const float* __restrict__ b1,
     const float* __restrict__ w2, const float* __restrict__ b2,
     const float* __restrict__ root_w, const float* __restrict__ conv_b,
     const float* __restrict__ ln_g, const float* __restrict__ ln_b,
     const float* __restrict__ aiw, const float* __restrict__ aib,
     const float* __restrict__ aow, const float* __restrict__ aob,
     const float* __restrict__ fw1, const float* __restrict__ fb1,
     const float* __restrict__ fw2, const float* __restrict__ fb2,
     const float* __restrict__ l1g, const float* __restrict__ l1b,
     const float* __restrict__ l2g, const float* __restrict__ l2b,
     const float* __restrict__ lw, const float* __restrict__ lb,
     const int* __restrict__ seq, const int* __restrict__ ei,
     float* __restrict__ out) {
    __shared__ float SB[4352];
    __shared__ float s_a[2][4], s_b[2][4], s_m[2], s_v[2];

    const int tid = threadIdx.x;
    const int g = blockIdx.x * NT + tid;
    const int* ss = seq;
    const int* sd = seq + NSEQ;
    const int* esrc = ei;
    const int* edst = ei + NEDGE;

    // ---- P0: zero histograms, B = [ee_w;ee_b] @ w1 (+b1), root_w -> Wc slot 10
    for (int n = g; n < NNODE; n += NTH) { g_degi[n] = 0; g_cnti[n] = 0; }
    for (int it = g; it < NLAY * 320; it += NTH) {
        int l = it / 320, r = it - l * 320;
        int j = r >> 5, tc = r & 31;
        float acc = (j == 9) ? b1[l * 32 + tc] : 0.f;
        for (int u = 0; u < 32; u++) {
            float a = (j < 9) ? eew[j * 32 + u] : eeb[u];
            acc += a * w1[(l * 32 + u) * 32 + tc];
        }
        g_Bm[it] = acc;
    }
    for (int idx = g; idx < NLAY * 16384; idx += NTH) {
        int l = idx >> 14, io = idx & 16383;
        int i = io >> 7, o = io & 127;
        g_Wc[(size_t)l * NHF * WCN + i * WCN + 1280 + o] = root_w[idx];
    }
    gbar();

    // ---- P1: degree/count histograms + Wc = B @ w2 (+b2)
    for (int e = g; e < NSEQ; e += NTH) atomicAdd(&g_degi[ss[e]], 1);
    for (int e = g; e < NEDGE; e += NTH) atomicAdd(&g_cnti[edst[e]], 1);
    for (int it = g; it < NLAY * 16384; it += NTH) {
        int l = it >> 14, io = it & 16383;
        float acc[10];
#pragma unroll
        for (int j = 0; j < 10; j++) acc[j] = 0.f;
        const float* wp = w2 + (size_t)l * 32 * 16384 + io;
        const float* bp = g_Bm + l * 320;
        for (int tc = 0; tc < 32; tc++) {
            float v = wp[(size_t)tc * 16384];
#pragma unroll
            for (int j = 0; j < 10; j++) acc[j] += bp[j * 32 + tc] * v;
        }
        acc[9] += b2[(size_t)l * 16384 + io];
        int i = io >> 7, o = io & 127;
        float* dst = g_Wc + (size_t)l * NHF * WCN + i * WCN + o;
#pragma unroll
        for (int j = 0; j < 10; j++) dst[j * 128] = acc[j];
    }
    gbar();

    // ---- P2: dinv, exclusive scan of edge counts (block 0)
    for (int n = g; n < NNODE; n += NTH) {
        int c = g_degi[n];
        g_dinv[n] = (c > 0) ? rsqrtf((float)c) : 0.f;
    }
    if (blockIdx.x == 0) {
        int* part = (int*)SB;
        int base = tid * 4;
        int v0[4]; int sloc = 0;
#pragma unroll
        for (int j = 0; j < 4; j++) {
            int idx = base + j;
            v0[j] = (idx < NNODE) ? g_cnti[idx] : 0;
            sloc += v0[j];
        }
        part[tid] = sloc;
        __syncthreads();
        for (int off = 1; off < 256; off <<= 1) {
            int xv = (tid >= off) ? part[tid - off] : 0;
            __syncthreads();
            part[tid] += xv;
            __syncthreads();
        }
        int run = (tid == 0) ? 0 : part[tid - 1];
#pragma unroll
        for (int j = 0; j < 4; j++) {
            int idx = base + j;
            run += v0[j];
            if (idx < NNODE) g_rp[idx + 1] = run;
        }
        if (tid == 0) g_rp[0] = 0;
    }
    gbar();

    // ---- P3: lap1 (tx1) + CSR fill
    for (int it = g; it < NNODE * NNF_; it += NTH) {
        int n = it / NNF_, f = it - n * NNF_;
        float dn = g_dinv[n];
        float acc = 0.f;
        for (int e = 0; e < NSEQ; e++) {
            if (sd[e] == n) {
                int s = ss[e];
                acc += -(g_dinv[s] * dn) * x[s * NNF_ + f];
            }
        }
        g_tx1[it] = acc;
    }
    {
        int gr = NTH - 1 - g;
        if (gr < NNODE && gr >= 0) {
            int p = g_rp[gr];
            for (int e = 0; e < NEDGE; e++)
                if (edst[e] == gr) g_eid[p++] = e;
        }
    }
    gbar();

    // ---- P4: lap2 (tx2)
    for (int it = g; it < NNODE * NNF_; it += NTH) {
        int n = it / NNF_, f = it - n * NNF_;
        float dn = g_dinv[n];
        float acc = 0.f;
        for (int e = 0; e < NSEQ; e++) {
            if (sd[e] == n) {
                int s = ss[e];
                acc += -(g_dinv[s] * dn) * g_tx1[s * NNF_ + f];
            }
        }
        g_tx2[it] = 2.f * acc - x[it];
    }
    gbar();

    // ---- P5: ChebConv output -> g_hin
    for (int it = g; it < NNODE * NHF; it += NTH) {
        int n = it >> 7, o = it & 127;
        const float* xr = x + n * NNF_;
        const float* t1 = g_tx1 + n * NNF_;
        const float* t2 = g_tx2 + n * NNF_;
        float acc = cheb_b[o];
#pragma unroll
        for (int f = 0; f < NNF_; f++) {
            acc += xr[f] * cheb_w[f * NHF + o];
            acc += t1[f] * cheb_w[2176 + f * NHF + o];
            acc += t2[f] * cheb_w[4352 + f * NHF + o];
        }
        g_hin[it] = acc;
    }
    gbar();

    // ---- conv layers ----
    for (int l = 0; l < NLAY; l++) {
        gemm_tiles(g_hin, g_Wc + (size_t)l * NHF * WCN, nullptr, g_P,
                   NNODE, WCN, NHF, 0, SB);
        gbar();
        // scatter + residual + LN + GELU (+ concat on last layer)
        {
            int half = tid >> 7, o = tid & 127;
            int w = (tid >> 5) & 3, lane = tid & 31;
            for (int ii = blockIdx.x; ii < NNODE / 2; ii += NB) {
                int n = ii * 2 + half;
                float acc = g_P[n * WCN + 1280 + o] + conv_b[l * 128 + o];
                int e0 = g_rp[n], e1 = g_rp[n + 1];
                for (int idx = e0; idx < e1; idx++) {
                    int e = g_eid[idx];
                    int s = esrc[e];
                    const float* zp = eattr + e * 9;
                    const float* Ps = g_P + s * WCN + o;
                    float m = Ps[1152];
#pragma unroll
                    for (int j = 0; j < 9; j++) m += zp[j] * Ps[j * 128];
                    acc += m;
                }
                float nh = acc + ((l > 0) ? g_h[n * 128 + o] : 0.f);
                g_h[n * 128 + o] = nh;
                float a = nh, b = nh * nh;
#pragma unroll
                for (int off = 16; off; off >>= 1) {
                    a += __shfl_down_sync(0xffffffffu, a, off);
                    b += __shfl_down_sync(0xffffffffu, b, off);
                }
                if (lane == 0) { s_a[half][w] = a; s_b[half][w] = b; }
                __syncthreads();
                if (o == 0) {
                    float ta = s_a[half][0] + s_a[half][1] + s_a[half][2] + s_a[half][3];
                    float tb = s_b[half][0] + s_b[half][1] + s_b[half][2] + s_b[half][3];
                    s_m[half] = ta * (1.f / 128.f);
                    s_v[half] = tb * (1.f / 128.f);
                }
                __syncthreads();
                float mean = s_m[half];
                float var = s_v[half] - mean * mean;
                int ni = (l + 1) % NLAY;
                float z = (nh - mean) * rsqrtf(var + EPSF) * ln_g[ni * 128 + o] + ln_b[ni * 128 + o];
                float act = geluf(z);
                if (l < NLAY - 1) {
                    g_hin[n * 128 + o] = act;
                } else {
                    g_t[n * DM + o] = act;
                    if (o < 32) {
                        int p = n % SEQL;
                        int i2 = o >> 1;
                        float div = expf((float)(2 * i2) * (-0.28782313662425576f));
                        float ang = (float)p * div;
                        g_t[n * DM + 128 + o] = (o & 1) ? cosf(ang) : sinf(ang);
                    }
                }
            }
        }
        gbar();
    }

    // ---- transformer: qkv layer 0 (tiled GEMM) ----
    gemm_tiles(g_t, aiw, aib, g_qkv, NNODE, 480, DM, 0, SB);
    gbar();

    for (int tl = 0; tl < 3; tl++) {
        // ---- attention: one (b,h) unit per block, online softmax ----
        {
            float* Ks = SB;
            float* Vs = SB + SEQL * 20;
            for (int u = blockIdx.x; u < 64; u += NB) {
                int b = u >> 3, h = u & 7;
                for (int i = tid; i < SEQL * 20; i += NT) {
                    int r = i / 20, d = i - r * 20;
                    int n = b * SEQL + r;
                    Ks[i] = g_qkv[n * 480 + 160 + h * 20 + d];
                    Vs[i] = g_qkv[n * 480 + 320 + h * 20 + d];
                }
                __syncthreads();
                if (tid < SEQL) {
                    int n = b * SEQL + tid;
                    float q[20];
#pragma unroll
                    for (int d = 0; d < 20; d++)
                        q[d] = g_qkv[n * 480 + h * 20 + d] * 0.22360679774997896f;
                    float m = -1e30f, lsum = 0.f, acc[20];
#pragma unroll
                    for (int d = 0; d < 20; d++) acc[d] = 0.f;
                    for (int k = 0; k < SEQL; k++) {
                        float s = 0.f;
#pragma unroll
                        for (int d = 0; d < 20; d++) s += q[d] * Ks[k * 20 + d];
                        float mn = fmaxf(m, s);
                        float corr = __expf(m - mn);
                        float p = __expf(s - mn);
                        lsum = lsum * corr + p;
#pragma unroll
                        for (int d = 0; d < 20; d++) acc[d] = acc[d] * corr + p * Vs[k * 20 + d];
                        m = mn;
                    }
                    float inv = 1.f / lsum;
#pragma unroll
                    for (int d = 0; d < 20; d++)
                        g_att[n * DM + h * 20 + d] = acc[d] * inv;
                }
                __syncthreads();
            }
        }
        gbar();

        // ---- X phase: out-proj + LN1 + FF + LN2 (+ next qkv / head), row-local
        {
            float* sT = SB;            // [8][160]
            float* sF = SB + 1280;     // [8][256]
            const float* Wo  = aow + (size_t)tl * 25600;
            const float* bo  = aob + tl * 160;
            const float* W1  = fw1 + (size_t)tl * 40960;
            const float* bb1 = fb1 + tl * 256;
            const float* W2  = fw2 + (size_t)tl * 40960;
            const float* bb2 = fb2 + tl * 160;
            const float* g1  = l1g + tl * 160;
            const float* be1 = l1b + tl * 160;
            const float* g2v = l2g + tl * 160;
            const float* be2 = l2b + tl * 160;
            int w = tid >> 5, lane = tid & 31;
            for (int rt = blockIdx.x; rt < SEQL; rt += NB) {  // 107 tiles of 8 rows
                int r0 = rt * 8;
                for (int i = tid; i < 8 * DM; i += NT) {
                    int r = i / DM, c = i - r * DM;
                    sT[i] = g_t[(r0 + r) * DM + c];
                }
                __syncthreads();
                int r = r0 + w;
                // step 1: out-proj + residual + LN1
                float acc[5], v[5];
#pragma unroll
                for (int j = 0; j < 5; j++) acc[j] = 0.f;
                for (int k = 0; k < DM; k++) {
                    float av = g_att[r * DM + k];
#pragma unroll
                    for (int j = 0; j < 5; j++)
                        acc[j] += av * Wo[k * 160 + lane + 32 * j];
                }
                float s1 = 0.f, s2 = 0.f;
#pragma unroll
                for (int j = 0; j < 5; j++) {
                    int c = lane + 32 * j;
                    v[j] = sT[w * DM + c] + acc[j] + bo[c];
                    s1 += v[j]; s2 += v[j] * v[j];
                }
#pragma unroll
                for (int off = 16; off; off >>= 1) {
                    s1 += __shfl_xor_sync(0xffffffffu, s1, off);
                    s2 += __shfl_xor_sync(0xffffffffu, s2, off);
                }
                float mean = s1 * (1.f / 160.f);
                float var = s2 * (1.f / 160.f) - mean * mean;
                float rstd = rsqrtf(var + EPSF);
#pragma unroll
                for (int j = 0; j < 5; j++) {
                    int c = lane + 32 * j;
                    sT[w * DM + c] = (v[j] - mean) * rstd * g1[c] + be1[c];
                }
                __syncwarp();
                // step 2: FF1 + relu
                float f[8];
#pragma unroll
                for (int j = 0; j < 8; j++) f[j] = 0.f;
                for (int k = 0; k < DM; k++) {
                    float a = sT[w * DM + k];
#pragma unroll
                    for (int j = 0; j < 8; j++)
                        f[j] += a * W1[k * 256 + lane + 32 * j];
                }
#pragma unroll
                for (int j = 0; j < 8; j++) {
                    int c = lane + 32 * j;
                    sF[w * 256 + c] = fmaxf(f[j] + bb1[c], 0.f);
                }
                __syncwarp();
                // step 3: FF2 + residual + LN2
#pragma unroll
                for (int j = 0; j < 5; j++) acc[j] = 0.f;
                for (int k = 0; k < 256; k++) {
                    float a = sF[w * 256 + k];
#pragma unroll
                    for (int j = 0; j < 5; j++)
                        acc[j] += a * W2[k * 160 + lane + 32 * j];
                }
                s1 = 0.f; s2 = 0.f;
#pragma unroll
                for (int j = 0; j < 5; j++) {
                    int c = lane + 32 * j;
                    v[j] = sT[w * DM + c] + acc[j] + bb2[c];
                    s1 += v[j]; s2 += v[j] * v[j];
                }
#pragma unroll
                for (int off = 16; off; off >>= 1) {
                    s1 += __shfl_xor_sync(0xffffffffu, s1, off);
                    s2 += __shfl_xor_sync(0xffffffffu, s2, off);
                }
                mean = s1 * (1.f / 160.f);
                var = s2 * (1.f / 160.f) - mean * mean;
                rstd = rsqrtf(var + EPSF);
#pragma unroll
                for (int j = 0; j < 5; j++) {
                    int c = lane + 32 * j;
                    float tn = (v[j] - mean) * rstd * g2v[c] + be2[c];
                    sT[w * DM + c] = tn;
                    g_t[r * DM + c] = tn;
                }
                __syncwarp();
                // step 4: next layer qkv, or final head
                if (tl < 2) {
                    const float* Wq = aiw + (size_t)(tl + 1) * 76800;
                    const float* bq = aib + (tl + 1) * 480;
                    float q[15];
#pragma unroll
                    for (int j = 0; j < 15; j++) q[j] = 0.f;
                    for (int k = 0; k < DM; k++) {
                        float a = sT[w * DM + k];
#pragma unroll
                        for (int j = 0; j < 15; j++)
                            q[j] += a * Wq[k * 480 + lane + 32 * j];
                    }
#pragma unroll
                    for (int j = 0; j < 15; j++) {
                        int c = lane + 32 * j;
                        g_qkv[r * 480 + c] = q[j] + bq[c];
                    }
                } else {
                    if (lane < 3) {
                        float a = lb[lane];
                        for (int k = 0; k < DM; k++)
                            a += sT[w * DM + k] * lw[k * 3 + lane];
                        out[r * 3 + lane] = a;
                    }
                }
                __syncthreads();
            }
        }
        if (tl < 2) gbar();
    }
}

// ---------------- host ----------------
extern "C" void kernel_launch(void* const* d_in, const int* in_sizes, int n_in,
                              void* d_out, int out_size) {
    mega<<<NB, NT>>>(
        (const float*)d_in[0],  (const float*)d_in[1],  (const float*)d_in[2],
        (const float*)d_in[3],  (const float*)d_in[4],  (const float*)d_in[5],
        (const float*)d_in[6],  (const float*)d_in[7],  (const float*)d_in[8],
        (const float*)d_in[9],  (const float*)d_in[10], (const float*)d_in[11],
        (const float*)d_in[12], (const float*)d_in[13], (const float*)d_in[14],
        (const float*)d_in[15], (const float*)d_in[16], (const float*)d_in[17],
        (const float*)d_in[18], (const float*)d_in[19], (const float*)d_in[20],
        (const float*)d_in[21], (const float*)d_in[22], (const float*)d_in[23],
        (const float*)d_in[24], (const float*)d_in[25], (const float*)d_in[26],
        (const float*)d_in[27], (const int*)d_in[28],   (const int*)d_in[29],
        (float*)d_out);
}

// round 5
// speedup vs baseline: 1.3110x; 1.1400x over previous
#include <cuda_runtime.h>
#include <math.h>

#define NNODE 856
#define NEDGE 2896
#define NSEQ  1696
#define NHF   128
#define NNF_  17
#define DM    160
#define SEQL  107
#define NLAY  10
#define WCN   1408
#define EPSF  1e-5f
#define NB    444
#define NT    256
#define NTH   (NB*NT)
#define BK    32

// ---------------- device scratch ----------------
__device__ float g_dinv[NNODE];
__device__ int   g_degi[NNODE];
__device__ float g_tx1[NNODE * NNF_];
__device__ float g_tx2[NNODE * NNF_];
__device__ float g_h[NNODE * NHF];
__device__ float g_hin[NNODE * NHF];
__device__ float g_Bm[NLAY * 320];
__device__ float g_Wc[NLAY * NHF * WCN];
__device__ float g_P[NNODE * WCN];
__device__ int   g_cnti[NNODE];
__device__ int   g_rp[NNODE + 1];
__device__ int   g_eid[NEDGE];
__device__ float g_t[NNODE * DM];
__device__ float g_qkv[NNODE * 480];
__device__ float g_att[NNODE * DM];
__device__ unsigned g_barcnt;
__device__ volatile unsigned g_bargen;

// ---------------- grid barrier (co-resident persistent grid) ----------------
__device__ __forceinline__ void gbar() {
    __syncthreads();
    __threadfence();                       // publish my writes to L2
    if (threadIdx.x == 0) {
        unsigned gen = g_bargen;
        if (atomicAdd(&g_barcnt, 1u) == NB - 1u) {
            g_barcnt = 0u;
            __threadfence();
            g_bargen = gen + 1u;
        } else {
            while (g_bargen == gen) __nanosleep(32);
        }
    }
    __syncthreads();
    __threadfence();                       // acquire: invalidate stale L1
}

__device__ __forceinline__ float geluf(float x) {
    return 0.5f * x * (1.0f + erff(x * 0.70710678118654752f));
}

// guarded float4 B-tile load: row always valid, col may exceed N
__device__ __forceinline__ float4 ldB4(const float* __restrict__ B, int row,
                                       int col, int N) {
    if (col + 3 < N) return *(const float4*)&B[row * N + col];
    float4 r = make_float4(0.f, 0.f, 0.f, 0.f);
    if (col     < N) r.x = B[row * N + col];
    if (col + 1 < N) r.y = B[row * N + col + 1];
    if (col + 2 < N) r.z = B[row * N + col + 2];
    return r;
}

// ---------------- tiled GEMM phase: C = act(A@B + bias) ----------------
// 64x64 tile, BK=32, register-staged pipeline. Requires K % 32 == 0.
__device__ void gemm_tiles(const float* __restrict__ A, const float* __restrict__ B,
                           const float* __restrict__ bias, float* __restrict__ C,
                           int M, int N, int K, int act, float* SB) {
    float* As = SB;              // [BK][68] padded
    float* Bs = SB + BK * 68;    // [BK][64]
    const int ntc = (N + 63) >> 6;
    const int ntiles = ((M + 63) >> 6) * ntc;
    const int tid = threadIdx.x;
    const int tx = tid & 15, ty = tid >> 4;
    const int arow = tid >> 3;           // 0..31 (+32 for u=1)
    const int ac   = (tid & 7) * 4;      // k offset
    const int bk   = tid >> 4;           // 0..15 (+16)
    const int bc   = (tid & 15) * 4;

    for (int t = blockIdx.x; t < ntiles; t += NB) {
        int tr = t / ntc;
        int rb = tr * 64, cb = (t - tr * ntc) * 64;
        float acc[4][4];
#pragma unroll
        for (int i = 0; i < 4; i++)
#pragma unroll
            for (int j = 0; j < 4; j++) acc[i][j] = 0.f;

        float ar[2][4];
        float4 br[2];
        // prologue: stage k0 = 0
#pragma unroll
        for (int u = 0; u < 2; u++) {
            int gr = rb + arow + u * 32;
            float4 t4 = (gr < M) ? *(const float4*)&A[gr * K + ac]
                                 : make_float4(0.f, 0.f, 0.f, 0.f);
            ar[u][0] = t4.x; ar[u][1] = t4.y; ar[u][2] = t4.z; ar[u][3] = t4.w;
            br[u] = ldB4(B, bk + u * 16, cb + bc, N);
        }

        for (int k0 = 0; k0 < K; k0 += BK) {
            __syncthreads();     // previous compute done before overwrite
#pragma unroll
            for (int u = 0; u < 2; u++) {
                int row = arow + u * 32;
#pragma unroll
                for (int j = 0; j < 4; j++)
                    As[(ac + j) * 68 + row] = ar[u][j];
                *(float4*)&Bs[(bk + u * 16) * 64 + bc] = br[u];
            }
            __syncthreads();
            if (k0 + BK < K) {
                int kn = k0 + BK;
#pragma unroll
                for (int u = 0; u < 2; u++) {
                    int gr = rb + arow + u * 32;
                    float4 t4 = (gr < M) ? *(const float4*)&A[gr * K + kn + ac]
                                         : make_float4(0.f, 0.f, 0.f, 0.f);
                    ar[u][0] = t4.x; ar[u][1] = t4.y; ar[u][2] = t4.z; ar[u][3] = t4.w;
                    br[u] = ldB4(B, kn + bk + u * 16, cb + bc, N);
                }
            }
#pragma unroll 8
            for (int k = 0; k < BK; k++) {
                float4 a4 = *(const float4*)&As[k * 68 + ty * 4];
                float4 b4 = *(const float4*)&Bs[k * 64 + tx * 4];
                float av[4] = {a4.x, a4.y, a4.z, a4.w};
                float bv[4] = {b4.x, b4.y, b4.z, b4.w};
#pragma unroll
                for (int i = 0; i < 4; i++)
#pragma unroll
                    for (int j = 0; j < 4; j++) acc[i][j] += av[i] * bv[j];
            }
        }
#pragma unroll
        for (int i = 0; i < 4; i++) {
            int r = rb + ty * 4 + i;
            if (r >= M) continue;
#pragma unroll
            for (int j = 0; j < 4; j++) {
                int c = cb + tx * 4 + j;
                if (c >= N) continue;
                float v = acc[i][j];
                if (bias) v += bias[c];
                if (act) v = fmaxf(v, 0.f);
                C[r * N + c] = v;
            }
        }
    }
}

// ---------------- the one kernel ----------------
__global__ void __launch_bounds__(NT, 3)
mega(const float* __restrict__ x, const float* __restrict__ eattr,
     const float* __restrict__ cheb_w, const float* __restrict__ cheb_b,
     const float* __restrict__ eew, const float* __restrict__ eeb,
     const float* __restrict__ w1, const float* __restrict__ b1,
     const float* __restrict__ w2, const float* __restrict__ b2,
     const float* __restrict__ root_w, const float* __restrict__ conv_b,
     const float* __restrict__ ln_g, const float* __restrict__ ln_b,
     const float* __restrict__ aiw, const float* __restrict__ aib,
     const float* __restrict__ aow, const float* __restrict__ aob,
     const float* __restrict__ fw1, const float* __restrict__ fb1,
     const float* __restrict__ fw2, const float* __restrict__ fb2,
     const float* __restrict__ l1g, const float* __restrict__ l1b,
     const float* __restrict__ l2g, const float* __restrict__ l2b,
     const float* __restrict__ lw, const float* __restrict__ lb,
     const int* __restrict__ seq, const int* __restrict__ ei,
     float* __restrict__ out) {
    __shared__ float SB[4352];
    __shared__ float s_a[2][4], s_b[2][4], s_m[2], s_v[2];

    const int tid = threadIdx.x;
    const int g = blockIdx.x * NT + tid;
    const int* ss = seq;
    const int* sd = seq + NSEQ;
    const int* esrc = ei;
    const int* edst = ei + NEDGE;

    // ---- P0: zero histograms, B = [ee_w;ee_b] @ w1 (+b1), root_w -> Wc slot 10
    for (int n = g; n < NNODE; n += NTH) { g_degi[n] = 0; g_cnti[n] = 0; }
    for (int it = g; it < NLAY * 320; it += NTH) {
        int l = it / 320, r = it - l * 320;
        int j = r >> 5, tc = r & 31;
        float acc = (j == 9) ? b1[l * 32 + tc] : 0.f;
        for (int u = 0; u < 32; u++) {
            float a = (j < 9) ? eew[j * 32 + u] : eeb[u];
            acc += a * w1[(l * 32 + u) * 32 + tc];
        }
        g_Bm[it] = acc;
    }
    for (int idx = g; idx < NLAY * 16384; idx += NTH) {
        int l = idx >> 14, io = idx & 16383;
        int i = io >> 7, o = io & 127;
        g_Wc[(size_t)l * NHF * WCN + i * WCN + 1280 + o] = root_w[idx];
    }
    gbar();

    // ---- P1: degree/count histograms + Wc = B @ w2 (+b2)
    for (int e = g; e < NSEQ; e += NTH) atomicAdd(&g_degi[ss[e]], 1);
    for (int e = g; e < NEDGE; e += NTH) atomicAdd(&g_cnti[edst[e]], 1);
    for (int it = g; it < NLAY * 16384; it += NTH) {
        int l = it >> 14, io = it & 16383;
        float acc[10];
#pragma unroll
        for (int j = 0; j < 10; j++) acc[j] = 0.f;
        const float* wp = w2 + (size_t)l * 32 * 16384 + io;
        const float* bp = g_Bm + l * 320;
#pragma unroll 8
        for (int tc = 0; tc < 32; tc++) {
            float v = wp[(size_t)tc * 16384];
#pragma unroll
            for (int j = 0; j < 10; j++) acc[j] += bp[j * 32 + tc] * v;
        }
        acc[9] += b2[(size_t)l * 16384 + io];
        int i = io >> 7, o = io & 127;
        float* dst = g_Wc + (size_t)l * NHF * WCN + i * WCN + o;
#pragma unroll
        for (int j = 0; j < 10; j++) dst[j * 128] = acc[j];
    }
    gbar();

    // ---- P2: dinv, exclusive scan of edge counts (block 0)
    for (int n = g; n < NNODE; n += NTH) {
        int c = g_degi[n];
        g_dinv[n] = (c > 0) ? rsqrtf((float)c) : 0.f;
    }
    if (blockIdx.x == 0) {
        int* part = (int*)SB;
        int base = tid * 4;
        int v0[4]; int sloc = 0;
#pragma unroll
        for (int j = 0; j < 4; j++) {
            int idx = base + j;
            v0[j] = (idx < NNODE) ? g_cnti[idx] : 0;
            sloc += v0[j];
        }
        part[tid] = sloc;
        __syncthreads();
        for (int off = 1; off < 256; off <<= 1) {
            int xv = (tid >= off) ? part[tid - off] : 0;
            __syncthreads();
            part[tid] += xv;
            __syncthreads();
        }
        int run = (tid == 0) ? 0 : part[tid - 1];
#pragma unroll
        for (int j = 0; j < 4; j++) {
            int idx = base + j;
            run += v0[j];
            if (idx < NNODE) g_rp[idx + 1] = run;
        }
        if (tid == 0) g_rp[0] = 0;
    }
    gbar();

    // ---- P3: lap1 (tx1) + CSR fill (disjoint thread ranges)
    for (int it = g; it < NNODE * NNF_; it += NTH) {
        int n = it / NNF_, f = it - n * NNF_;
        float dn = g_dinv[n];
        float acc = 0.f;
        for (int e = 0; e < NSEQ; e++) {
            if (sd[e] == n) {
                int s = ss[e];
                acc += -(g_dinv[s] * dn) * x[s * NNF_ + f];
            }
        }
        g_tx1[it] = acc;
    }
    {
        int gr = NTH - 1 - g;
        if (gr < NNODE && gr >= 0) {
            int p = g_rp[gr];
            for (int e = 0; e < NEDGE; e++)
                if (edst[e] == gr) g_eid[p++] = e;
        }
    }
    gbar();

    // ---- P4: lap2 (tx2)
    for (int it = g; it < NNODE * NNF_; it += NTH) {
        int n = it / NNF_, f = it - n * NNF_;
        float dn = g_dinv[n];
        float acc = 0.f;
        for (int e = 0; e < NSEQ; e++) {
            if (sd[e] == n) {
                int s = ss[e];
                acc += -(g_dinv[s] * dn) * g_tx1[s * NNF_ + f];
            }
        }
        g_tx2[it] = 2.f * acc - x[it];
    }
    gbar();

    // ---- P5: ChebConv output -> g_hin
    for (int it = g; it < NNODE * NHF; it += NTH) {
        int n = it >> 7, o = it & 127;
        const float* xr = x + n * NNF_;
        const float* t1 = g_tx1 + n * NNF_;
        const float* t2 = g_tx2 + n * NNF_;
        float acc = cheb_b[o];
#pragma unroll
        for (int f = 0; f < NNF_; f++) {
            acc += xr[f] * cheb_w[f * NHF + o];
            acc += t1[f] * cheb_w[2176 + f * NHF + o];
            acc += t2[f] * cheb_w[4352 + f * NHF + o];
        }
        g_hin[it] = acc;
    }
    gbar();

    // ---- conv layers ----
    for (int l = 0; l < NLAY; l++) {
        gemm_tiles(g_hin, g_Wc + (size_t)l * NHF * WCN, nullptr, g_P,
                   NNODE, WCN, NHF, 0, SB);
        gbar();
        // scatter + residual + LN + GELU (+ concat on last layer)
        {
            int half = tid >> 7, o = tid & 127;
            int w = (tid >> 5) & 3, lane = tid & 31;
            for (int ii = blockIdx.x; ii < NNODE / 2; ii += NB) {
                int n = ii * 2 + half;
                float acc = g_P[n * WCN + 1280 + o] + conv_b[l * 128 + o];
                int e0 = g_rp[n], e1 = g_rp[n + 1];
                for (int idx = e0; idx < e1; idx++) {
                    int e = g_eid[idx];
                    int s = esrc[e];
                    const float* zp = eattr + e * 9;
                    const float* Ps = g_P + s * WCN + o;
                    float m = Ps[1152];
#pragma unroll
                    for (int j = 0; j < 9; j++) m += zp[j] * Ps[j * 128];
                    acc += m;
                }
                float nh = acc + ((l > 0) ? g_h[n * 128 + o] : 0.f);
                g_h[n * 128 + o] = nh;
                float a = nh, b = nh * nh;
#pragma unroll
                for (int off = 16; off; off >>= 1) {
                    a += __shfl_down_sync(0xffffffffu, a, off);
                    b += __shfl_down_sync(0xffffffffu, b, off);
                }
                if (lane == 0) { s_a[half][w] = a; s_b[half][w] = b; }
                __syncthreads();
                if (o == 0) {
                    float ta = s_a[half][0] + s_a[half][1] + s_a[half][2] + s_a[half][3];
                    float tb = s_b[half][0] + s_b[half][1] + s_b[half][2] + s_b[half][3];
                    s_m[half] = ta * (1.f / 128.f);
                    s_v[half] = tb * (1.f / 128.f);
                }
                __syncthreads();
                float mean = s_m[half];
                float var = s_v[half] - mean * mean;
                int ni = (l + 1) % NLAY;
                float z = (nh - mean) * rsqrtf(var + EPSF) * ln_g[ni * 128 + o] + ln_b[ni * 128 + o];
                float act = geluf(z);
                if (l < NLAY - 1) {
                    g_hin[n * 128 + o] = act;
                } else {
                    g_t[n * DM + o] = act;
                    if (o < 32) {
                        int p = n % SEQL;
                        int i2 = o >> 1;
                        float div = expf((float)(2 * i2) * (-0.28782313662425576f));
                        float ang = (float)p * div;
                        g_t[n * DM + 128 + o] = (o & 1) ? cosf(ang) : sinf(ang);
                    }
                }
            }
        }
        gbar();
    }

    // ---- transformer: qkv layer 0 (tiled GEMM) ----
    gemm_tiles(g_t, aiw, aib, g_qkv, NNODE, 480, DM, 0, SB);
    gbar();

    for (int tl = 0; tl < 3; tl++) {
        // ---- attention: 128 units (b, h, half), online softmax ----
        {
            float* Ks = SB;
            float* Vs = SB + SEQL * 20;
            for (int u = blockIdx.x; u < 128; u += NB) {
                int b = u >> 4, rem = u & 15;
                int h = rem >> 1, half = rem & 1;
                for (int i = tid; i < SEQL * 20; i += NT) {
                    int r = i / 20, d = i - r * 20;
                    int n = b * SEQL + r;
                    Ks[i] = g_qkv[n * 480 + 160 + h * 20 + d];
                    Vs[i] = g_qkv[n * 480 + 320 + h * 20 + d];
                }
                __syncthreads();
                int cnt = half ? 53 : 54;
                if (tid < cnt) {
                    int n = b * SEQL + half * 54 + tid;
                    float q[20];
#pragma unroll
                    for (int d = 0; d < 20; d++)
                        q[d] = g_qkv[n * 480 + h * 20 + d] * 0.22360679774997896f;
                    float m = -1e30f, lsum = 0.f, acc[20];
#pragma unroll
                    for (int d = 0; d < 20; d++) acc[d] = 0.f;
                    for (int k = 0; k < SEQL; k++) {
                        float s = 0.f;
#pragma unroll
                        for (int d = 0; d < 20; d++) s += q[d] * Ks[k * 20 + d];
                        float mn = fmaxf(m, s);
                        float corr = __expf(m - mn);
                        float p = __expf(s - mn);
                        lsum = lsum * corr + p;
#pragma unroll
                        for (int d = 0; d < 20; d++) acc[d] = acc[d] * corr + p * Vs[k * 20 + d];
                        m = mn;
                    }
                    float inv = 1.f / lsum;
#pragma unroll
                    for (int d = 0; d < 20; d++)
                        g_att[n * DM + h * 20 + d] = acc[d] * inv;
                }
                __syncthreads();
            }
        }
        gbar();

        // ---- X phase: out-proj + LN1 + FF + LN2 (+ next qkv / head), row-local
        {
            float* sT = SB;            // [8][160]
            float* sF = SB + 1280;     // [8][256]
            const float* Wo  = aow + (size_t)tl * 25600;
            const float* bo  = aob + tl * 160;
            const float* W1  = fw1 + (size_t)tl * 40960;
            const float* bb1 = fb1 + tl * 256;
            const float* W2  = fw2 + (size_t)tl * 40960;
            const float* bb2 = fb2 + tl * 160;
            const float* g1  = l1g + tl * 160;
            const float* be1 = l1b + tl * 160;
            const float* g2v = l2g + tl * 160;
            const float* be2 = l2b + tl * 160;
            int w = tid >> 5, lane = tid & 31;
            for (int rt = blockIdx.x; rt < SEQL; rt += NB) {  // 107 tiles of 8 rows
                int r0 = rt * 8;
                for (int i = tid; i < 8 * DM; i += NT) {
                    int r = i / DM, c = i - r * DM;
                    sT[i] = g_t[(r0 + r) * DM + c];
                }
                __syncthreads();
                int r = r0 + w;
                // step 1: out-proj + residual + LN1
                float acc[5], v[5];
#pragma unroll
                for (int j = 0; j < 5; j++) acc[j] = 0.f;
                for (int k = 0; k < DM; k++) {
                    float av = g_att[r * DM + k];
#pragma unroll
                    for (int j = 0; j < 5; j++)
                        acc[j] += av * Wo[k * 160 + lane + 32 * j];
                }
                float s1 = 0.f, s2 = 0.f;
#pragma unroll
                for (int j = 0; j < 5; j++) {
                    int c = lane + 32 * j;
                    v[j] = sT[w * DM + c] + acc[j] + bo[c];
                    s1 += v[j]; s2 += v[j] * v[j];
                }
#pragma unroll
                for (int off = 16; off; off >>= 1) {
                    s1 += __shfl_xor_sync(0xffffffffu, s1, off);
                    s2 += __shfl_xor_sync(0xffffffffu, s2, off);
                }
                float mean = s1 * (1.f / 160.f);
                float var = s2 * (1.f / 160.f) - mean * mean;
                float rstd = rsqrtf(var + EPSF);
#pragma unroll
                for (int j = 0; j < 5; j++) {
                    int c = lane + 32 * j;
                    sT[w * DM + c] = (v[j] - mean) * rstd * g1[c] + be1[c];
                }
                __syncwarp();
                // step 2: FF1 + relu
                float f[8];
#pragma unroll
                for (int j = 0; j < 8; j++) f[j] = 0.f;
                for (int k = 0; k < DM; k++) {
                    float a = sT[w * DM + k];
#pragma unroll
                    for (int j = 0; j < 8; j++)
                        f[j] += a * W1[k * 256 + lane + 32 * j];
                }
#pragma unroll
                for (int j = 0; j < 8; j++) {
                    int c = lane + 32 * j;
                    sF[w * 256 + c] = fmaxf(f[j] + bb1[c], 0.f);
                }
                __syncwarp();
                // step 3: FF2 + residual + LN2
#pragma unroll
                for (int j = 0; j < 5; j++) acc[j] = 0.f;
                for (int k = 0; k < 256; k++) {
                    float a = sF[w * 256 + k];
#pragma unroll
                    for (int j = 0; j < 5; j++)
                        acc[j] += a * W2[k * 160 + lane + 32 * j];
                }
                s1 = 0.f; s2 = 0.f;
#pragma unroll
                for (int j = 0; j < 5; j++) {
                    int c = lane + 32 * j;
                    v[j] = sT[w * DM + c] + acc[j] + bb2[c];
                    s1 += v[j]; s2 += v[j] * v[j];
                }
#pragma unroll
                for (int off = 16; off; off >>= 1) {
                    s1 += __shfl_xor_sync(0xffffffffu, s1, off);
                    s2 += __shfl_xor_sync(0xffffffffu, s2, off);
                }
                mean = s1 * (1.f / 160.f);
                var = s2 * (1.f / 160.f) - mean * mean;
                rstd = rsqrtf(var + EPSF);
#pragma unroll
                for (int j = 0; j < 5; j++) {
                    int c = lane + 32 * j;
                    float tn = (v[j] - mean) * rstd * g2v[c] + be2[c];
                    sT[w * DM + c] = tn;
                    g_t[r * DM + c] = tn;
                }
                __syncwarp();
                // step 4: next layer qkv, or final head
                if (tl < 2) {
                    const float* Wq = aiw + (size_t)(tl + 1) * 76800;
                    const float* bq = aib + (tl + 1) * 480;
                    float q[15];
#pragma unroll
                    for (int j = 0; j < 15; j++) q[j] = 0.f;
                    for (int k = 0; k < DM; k++) {
                        float a = sT[w * DM + k];
#pragma unroll
                        for (int j = 0; j < 15; j++)
                            q[j] += a * Wq[k * 480 + lane + 32 * j];
                    }
#pragma unroll
                    for (int j = 0; j < 15; j++) {
                        int c = lane + 32 * j;
                        g_qkv[r * 480 + c] = q[j] + bq[c];
                    }
                } else {
                    if (lane < 3) {
                        float a = lb[lane];
                        for (int k = 0; k < DM; k++)
                            a += sT[w * DM + k] * lw[k * 3 + lane];
                        out[r * 3 + lane] = a;
                    }
                }
                __syncthreads();
            }
        }
        if (tl < 2) gbar();
    }
}

// ---------------- host ----------------
extern "C" void kernel_launch(void* const* d_in, const int* in_sizes, int n_in,
                              void* d_out, int out_size) {
    mega<<<NB, NT>>>(
        (const float*)d_in[0],  (const float*)d_in[1],  (const float*)d_in[2],
        (const float*)d_in[3],  (const float*)d_in[4],  (const float*)d_in[5],
        (const float*)d_in[6],  (const float*)d_in[7],  (const float*)d_in[8],
        (const float*)d_in[9],  (const float*)d_in[10], (const float*)d_in[11],
        (const float*)d_in[12], (const float*)d_in[13], (const float*)d_in[14],
        (const float*)d_in[15], (const float*)d_in[16], (const float*)d_in[17],
        (const float*)d_in[18], (const float*)d_in[19], (const float*)d_in[20],
        (const float*)d_in[21], (const float*)d_in[22], (const float*)d_in[23],
        (const float*)d_in[24], (const float*)d_in[25], (const float*)d_in[26],
        (const float*)d_in[27], (const int*)d_in[28],   (const int*)d_in[29],
        (float*)d_out);
}